// round 3
// baseline (speedup 1.0000x reference)
#include <cuda_runtime.h>

// Problem constants
#define Lq   2048
#define Bb   4
#define Ee   1024
#define Hh   16
#define HD   64
#define BHh  64            // Bb*Hh
#define Mrows (Lq*Bb)      // 8192

// One consolidated scratch symbol: [Q | K | V | O], each (BH, L, HD) fp32.
#define SEG ((size_t)BHh * Lq * HD)
__device__ float g_scratch[4 * SEG];

// ---------------------------------------------------------------------------
// Kernel 1: QKV projection.  C[m,n] = sum_k X[m,k] * W[n,k] + bias[n]
// X = q/k/v viewed as (M=8192, E) row-major (m = l*B + b).
// Output written transposed into (BH, L, HD) layout; Q scaled by 1/8.
// 128x128 tile, BK=8, 256 threads, 8x8 per thread.
// ---------------------------------------------------------------------------
__global__ __launch_bounds__(256)
void proj_kernel(const float* __restrict__ q,
                 const float* __restrict__ k,
                 const float* __restrict__ v,
                 const float* __restrict__ w,     // (3E, E)
                 const float* __restrict__ bias)  // (3E,)
{
    const int z = blockIdx.z;                    // 0=Q, 1=K, 2=V
    const float* X   = (z == 0) ? q : (z == 1) ? k : v;
    float*       Out = g_scratch + (size_t)z * SEG;
    const float* W   = w + z * Ee * Ee;
    const float* bz  = bias + z * Ee;
    const float scale = (z == 0) ? 0.125f : 1.0f;

    __shared__ __align__(16) float As[8][128];
    __shared__ __align__(16) float Bs[8][128];

    const int bm  = blockIdx.y * 128;
    const int bn  = blockIdx.x * 128;
    const int tid = threadIdx.x;
    const int tx  = tid & 15;
    const int ty  = tid >> 4;

    const int lrow = tid >> 1;          // 0..127
    const int lcol = (tid & 1) * 4;     // 0 or 4

    float acc[8][8];
#pragma unroll
    for (int i = 0; i < 8; i++)
#pragma unroll
        for (int j = 0; j < 8; j++) acc[i][j] = 0.0f;

    for (int k0 = 0; k0 < Ee; k0 += 8) {
        float4 a4 = *(const float4*)(X + (size_t)(bm + lrow) * Ee + k0 + lcol);
        As[lcol + 0][lrow] = a4.x;
        As[lcol + 1][lrow] = a4.y;
        As[lcol + 2][lrow] = a4.z;
        As[lcol + 3][lrow] = a4.w;
        float4 b4 = *(const float4*)(W + (size_t)(bn + lrow) * Ee + k0 + lcol);
        Bs[lcol + 0][lrow] = b4.x;
        Bs[lcol + 1][lrow] = b4.y;
        Bs[lcol + 2][lrow] = b4.z;
        Bs[lcol + 3][lrow] = b4.w;
        __syncthreads();

        // Software-pipelined over kk: prefetch regs for kk+1 while FMAs run.
        float4 a0 = *(const float4*)(&As[0][ty * 8]);
        float4 a1 = *(const float4*)(&As[0][ty * 8 + 4]);
        float4 b0 = *(const float4*)(&Bs[0][tx * 8]);
        float4 b1 = *(const float4*)(&Bs[0][tx * 8 + 4]);
#pragma unroll
        for (int kk = 0; kk < 8; kk++) {
            float ar[8], br[8];
            ar[0]=a0.x; ar[1]=a0.y; ar[2]=a0.z; ar[3]=a0.w;
            ar[4]=a1.x; ar[5]=a1.y; ar[6]=a1.z; ar[7]=a1.w;
            br[0]=b0.x; br[1]=b0.y; br[2]=b0.z; br[3]=b0.w;
            br[4]=b1.x; br[5]=b1.y; br[6]=b1.z; br[7]=b1.w;
            if (kk < 7) {
                a0 = *(const float4*)(&As[kk + 1][ty * 8]);
                a1 = *(const float4*)(&As[kk + 1][ty * 8 + 4]);
                b0 = *(const float4*)(&Bs[kk + 1][tx * 8]);
                b1 = *(const float4*)(&Bs[kk + 1][tx * 8 + 4]);
            }
#pragma unroll
            for (int i = 0; i < 8; i++)
#pragma unroll
                for (int j = 0; j < 8; j++)
                    acc[i][j] += ar[i] * br[j];
        }
        __syncthreads();
    }

    // Epilogue: out[(b*H + h)*L*HD + l*HD + d] = scale * (acc + bias[n])
#pragma unroll
    for (int i = 0; i < 8; i++) {
        const int m = bm + ty * 8 + i;
        const int l = m >> 2;           // m / B
        const int b = m & 3;            // m % B
#pragma unroll
        for (int j = 0; j < 8; j++) {
            const int n = bn + tx * 8 + j;
            const int h = n >> 6;
            const int d = n & 63;
            Out[((size_t)(b * Hh + h) * Lq + l) * HD + d] =
                scale * (acc[i][j] + bz[n]);
        }
    }
}

// ---------------------------------------------------------------------------
// Kernel 2: flash attention, fp32. One block = (head, 128 q-rows).
// Each thread owns one q row (q/o in registers). K/V tiles of 64 in smem.
// Online softmax with 16-wide score chunks kept in registers.
// ---------------------------------------------------------------------------
__global__ __launch_bounds__(128)
void attn_kernel()
{
    const float* gQ = g_scratch;
    const float* gK = g_scratch + SEG;
    const float* gV = g_scratch + 2 * SEG;
    float*       gO = g_scratch + 3 * SEG;

    const int head = blockIdx.y;
    const int q0   = blockIdx.x * 128;
    const int tid  = threadIdx.x;

    __shared__ __align__(16) float Ks[64][64];
    __shared__ __align__(16) float Vs[64][64];

    // Load my q row into registers (already scaled by 1/8 in projection).
    float4 qr[16];
    {
        const float4* Qp = (const float4*)(gQ + ((size_t)head * Lq + q0 + tid) * HD);
#pragma unroll
        for (int i = 0; i < 16; i++) qr[i] = Qp[i];
    }

    float4 o[16];
#pragma unroll
    for (int i = 0; i < 16; i++) o[i] = make_float4(0.f, 0.f, 0.f, 0.f);
    float mval = -1e30f, lsum = 0.0f;

    const int jr = tid >> 1;            // 0..63 tile row for coop load
    const int c0 = (tid & 1) * 32;      // half-row offset

    for (int kt = 0; kt < Lq; kt += 64) {
        const float* kp = gK + ((size_t)head * Lq + kt + jr) * HD + c0;
        const float* vp = gV + ((size_t)head * Lq + kt + jr) * HD + c0;
#pragma unroll
        for (int i = 0; i < 8; i++) {
            *(float4*)(&Ks[jr][c0 + i * 4]) = *(const float4*)(kp + i * 4);
            *(float4*)(&Vs[jr][c0 + i * 4]) = *(const float4*)(vp + i * 4);
        }
        __syncthreads();

#pragma unroll 1
        for (int jc = 0; jc < 64; jc += 16) {
            float s[16];
            float cmax = -1e30f;
#pragma unroll
            for (int jj = 0; jj < 16; jj++) {
                float a = 0.0f;
                const float4* k4 = (const float4*)(&Ks[jc + jj][0]);
#pragma unroll
                for (int d4 = 0; d4 < 16; d4++) {
                    float4 kv = k4[d4];
                    a += qr[d4].x * kv.x; a += qr[d4].y * kv.y;
                    a += qr[d4].z * kv.z; a += qr[d4].w * kv.w;
                }
                s[jj] = a;
                cmax = fmaxf(cmax, a);
            }
            if (cmax > mval) {
                const float corr = __expf(mval - cmax);
                mval = cmax;
                lsum *= corr;
#pragma unroll
                for (int i = 0; i < 16; i++) {
                    o[i].x *= corr; o[i].y *= corr;
                    o[i].z *= corr; o[i].w *= corr;
                }
            }
#pragma unroll
            for (int jj = 0; jj < 16; jj++) {
                const float p = __expf(s[jj] - mval);
                lsum += p;
                const float4* v4 = (const float4*)(&Vs[jc + jj][0]);
#pragma unroll
                for (int d4 = 0; d4 < 16; d4++) {
                    float4 vv = v4[d4];
                    o[d4].x += p * vv.x; o[d4].y += p * vv.y;
                    o[d4].z += p * vv.z; o[d4].w += p * vv.w;
                }
            }
        }
        __syncthreads();
    }

    const float inv = 1.0f / lsum;
    float4* op = (float4*)(gO + ((size_t)head * Lq + q0 + tid) * HD);
#pragma unroll
    for (int i = 0; i < 16; i++) {
        float4 t;
        t.x = o[i].x * inv; t.y = o[i].y * inv;
        t.z = o[i].z * inv; t.w = o[i].w * inv;
        op[i] = t;
    }
}

// ---------------------------------------------------------------------------
// Kernel 3: output projection. A[m,k] gathered from g_O (BH,L,HD) layout;
// C[m,n] = sum_k A[m,k]*out_w[n,k] + out_b[n]; out (L,B,E) flat row m.
// ---------------------------------------------------------------------------
__global__ __launch_bounds__(256)
void outproj_kernel(const float* __restrict__ ow,
                    const float* __restrict__ ob,
                    float* __restrict__ out)
{
    const float* gO = g_scratch + 3 * SEG;

    __shared__ __align__(16) float As[8][128];
    __shared__ __align__(16) float Bs[8][128];

    const int bm  = blockIdx.y * 128;
    const int bn  = blockIdx.x * 128;
    const int tid = threadIdx.x;
    const int tx  = tid & 15;
    const int ty  = tid >> 4;

    const int lrow = tid >> 1;
    const int lcol = (tid & 1) * 4;

    float acc[8][8];
#pragma unroll
    for (int i = 0; i < 8; i++)
#pragma unroll
        for (int j = 0; j < 8; j++) acc[i][j] = 0.0f;

    const int m_l  = (bm + lrow);
    const int lA   = m_l >> 2;     // l
    const int bA   = m_l & 3;      // b

    for (int k0 = 0; k0 < Ee; k0 += 8) {
        const int kidx = k0 + lcol;
        const int h = kidx >> 6;
        const int d = kidx & 63;
        float4 a4 = *(const float4*)(gO + ((size_t)(bA * Hh + h) * Lq + lA) * HD + d);
        As[lcol + 0][lrow] = a4.x;
        As[lcol + 1][lrow] = a4.y;
        As[lcol + 2][lrow] = a4.z;
        As[lcol + 3][lrow] = a4.w;
        float4 b4 = *(const float4*)(ow + (size_t)(bn + lrow) * Ee + k0 + lcol);
        Bs[lcol + 0][lrow] = b4.x;
        Bs[lcol + 1][lrow] = b4.y;
        Bs[lcol + 2][lrow] = b4.z;
        Bs[lcol + 3][lrow] = b4.w;
        __syncthreads();

        float4 a0 = *(const float4*)(&As[0][ty * 8]);
        float4 a1 = *(const float4*)(&As[0][ty * 8 + 4]);
        float4 b0 = *(const float4*)(&Bs[0][tx * 8]);
        float4 b1 = *(const float4*)(&Bs[0][tx * 8 + 4]);
#pragma unroll
        for (int kk = 0; kk < 8; kk++) {
            float ar[8], br[8];
            ar[0]=a0.x; ar[1]=a0.y; ar[2]=a0.z; ar[3]=a0.w;
            ar[4]=a1.x; ar[5]=a1.y; ar[6]=a1.z; ar[7]=a1.w;
            br[0]=b0.x; br[1]=b0.y; br[2]=b0.z; br[3]=b0.w;
            br[4]=b1.x; br[5]=b1.y; br[6]=b1.z; br[7]=b1.w;
            if (kk < 7) {
                a0 = *(const float4*)(&As[kk + 1][ty * 8]);
                a1 = *(const float4*)(&As[kk + 1][ty * 8 + 4]);
                b0 = *(const float4*)(&Bs[kk + 1][tx * 8]);
                b1 = *(const float4*)(&Bs[kk + 1][tx * 8 + 4]);
            }
#pragma unroll
            for (int i = 0; i < 8; i++)
#pragma unroll
                for (int j = 0; j < 8; j++)
                    acc[i][j] += ar[i] * br[j];
        }
        __syncthreads();
    }

#pragma unroll
    for (int i = 0; i < 8; i++) {
        const int m = bm + ty * 8 + i;
#pragma unroll
        for (int j = 0; j < 8; j++) {
            const int n = bn + tx * 8 + j;
            out[(size_t)m * Ee + n] = acc[i][j] + ob[n];
        }
    }
}

// ---------------------------------------------------------------------------
// Launch
// Inputs: 0=q, 1=k, 2=v, 3=in_proj_weight, 4=in_proj_bias, 5=out_w, 6=out_b
// ---------------------------------------------------------------------------
extern "C" void kernel_launch(void* const* d_in, const int* in_sizes, int n_in,
                              void* d_out, int out_size)
{
    const float* q  = (const float*)d_in[0];
    const float* k  = (const float*)d_in[1];
    const float* v  = (const float*)d_in[2];
    const float* w  = (const float*)d_in[3];
    const float* bi = (const float*)d_in[4];
    const float* ow = (const float*)d_in[5];
    const float* ob = (const float*)d_in[6];
    float* out = (float*)d_out;

    dim3 gp(Ee / 128, Mrows / 128, 3);
    proj_kernel<<<gp, 256>>>(q, k, v, w, bi);

    dim3 ga(Lq / 128, BHh);
    attn_kernel<<<ga, 128>>>();

    dim3 go(Ee / 128, Mrows / 128);
    outproj_kernel<<<go, 256>>>(ow, ob, out);
}

// round 4
// speedup vs baseline: 1.0099x; 1.0099x over previous
#include <cuda_runtime.h>

// Problem constants
#define Lq   2048
#define Bb   4
#define Ee   1024
#define Hh   16
#define HD   64
#define BHh  64            // Bb*Hh
#define Mrows (Lq*Bb)      // 8192

// One consolidated scratch symbol: [Q | K | V | O], each (BH, L, HD) fp32.
#define SEG ((size_t)BHh * Lq * HD)
__device__ float g_scratch[4 * SEG];

// ---------------------------------------------------------------------------
// Packed fp32x2 helpers (Blackwell FFMA2 path — only reachable via PTX)
// ---------------------------------------------------------------------------
typedef unsigned long long u64;

__device__ __forceinline__ u64 pack2(float lo, float hi) {
    u64 r; asm("mov.b64 %0, {%1, %2};" : "=l"(r) : "f"(lo), "f"(hi)); return r;
}
__device__ __forceinline__ float2 unpack2(u64 v) {
    float2 f; asm("mov.b64 {%0, %1}, %2;" : "=f"(f.x), "=f"(f.y) : "l"(v)); return f;
}
__device__ __forceinline__ u64 ffma2(u64 a, u64 b, u64 c) {
    u64 d; asm("fma.rn.f32x2 %0, %1, %2, %3;" : "=l"(d) : "l"(a), "l"(b), "l"(c)); return d;
}
__device__ __forceinline__ u64 fmul2(u64 a, u64 b) {
    u64 d; asm("mul.rn.f32x2 %0, %1, %2;" : "=l"(d) : "l"(a), "l"(b)); return d;
}

// ---------------------------------------------------------------------------
// Kernel 1: QKV projection.  C[m,n] = sum_k X[m,k] * W[n,k] + bias[n]
// 128x128 tile, BK=8, 256 threads, 8x8 per thread (acc packed along j).
// Output transposed into (BH, L, HD) layout; Q scaled by 1/8.
// ---------------------------------------------------------------------------
__global__ __launch_bounds__(256)
void proj_kernel(const float* __restrict__ q,
                 const float* __restrict__ k,
                 const float* __restrict__ v,
                 const float* __restrict__ w,     // (3E, E)
                 const float* __restrict__ bias)  // (3E,)
{
    const int z = blockIdx.z;                    // 0=Q, 1=K, 2=V
    const float* X   = (z == 0) ? q : (z == 1) ? k : v;
    float*       Out = g_scratch + (size_t)z * SEG;
    const float* W   = w + z * Ee * Ee;
    const float* bz  = bias + z * Ee;
    const float scale = (z == 0) ? 0.125f : 1.0f;

    __shared__ __align__(16) float As[8][128];
    __shared__ __align__(16) float Bs[8][128];

    const int bm  = blockIdx.y * 128;
    const int bn  = blockIdx.x * 128;
    const int tid = threadIdx.x;
    const int tx  = tid & 15;
    const int ty  = tid >> 4;

    const int lrow = tid >> 1;          // 0..127
    const int lcol = (tid & 1) * 4;     // 0 or 4

    u64 acc2[8][4];
#pragma unroll
    for (int i = 0; i < 8; i++)
#pragma unroll
        for (int j = 0; j < 4; j++) acc2[i][j] = 0ull;

    for (int k0 = 0; k0 < Ee; k0 += 8) {
        float4 a4 = *(const float4*)(X + (size_t)(bm + lrow) * Ee + k0 + lcol);
        As[lcol + 0][lrow] = a4.x;
        As[lcol + 1][lrow] = a4.y;
        As[lcol + 2][lrow] = a4.z;
        As[lcol + 3][lrow] = a4.w;
        float4 b4 = *(const float4*)(W + (size_t)(bn + lrow) * Ee + k0 + lcol);
        Bs[lcol + 0][lrow] = b4.x;
        Bs[lcol + 1][lrow] = b4.y;
        Bs[lcol + 2][lrow] = b4.z;
        Bs[lcol + 3][lrow] = b4.w;
        __syncthreads();

        // Software pipeline: prefetch regs for kk+1 while FMAs run.
        float4 a0 = *(const float4*)(&As[0][ty * 8]);
        float4 a1 = *(const float4*)(&As[0][ty * 8 + 4]);
        ulonglong2 bb0 = *(const ulonglong2*)(&Bs[0][tx * 8]);
        ulonglong2 bb1 = *(const ulonglong2*)(&Bs[0][tx * 8 + 4]);
#pragma unroll
        for (int kk = 0; kk < 8; kk++) {
            u64 ab[8];
            ab[0] = pack2(a0.x, a0.x); ab[1] = pack2(a0.y, a0.y);
            ab[2] = pack2(a0.z, a0.z); ab[3] = pack2(a0.w, a0.w);
            ab[4] = pack2(a1.x, a1.x); ab[5] = pack2(a1.y, a1.y);
            ab[6] = pack2(a1.z, a1.z); ab[7] = pack2(a1.w, a1.w);
            u64 br2[4];
            br2[0] = bb0.x; br2[1] = bb0.y; br2[2] = bb1.x; br2[3] = bb1.y;
            if (kk < 7) {
                a0  = *(const float4*)(&As[kk + 1][ty * 8]);
                a1  = *(const float4*)(&As[kk + 1][ty * 8 + 4]);
                bb0 = *(const ulonglong2*)(&Bs[kk + 1][tx * 8]);
                bb1 = *(const ulonglong2*)(&Bs[kk + 1][tx * 8 + 4]);
            }
#pragma unroll
            for (int i = 0; i < 8; i++)
#pragma unroll
                for (int j = 0; j < 4; j++)
                    acc2[i][j] = ffma2(ab[i], br2[j], acc2[i][j]);
        }
        __syncthreads();
    }

    // Epilogue: out[(b*H + h)*L*HD + l*HD + d] = scale * (acc + bias[n])
#pragma unroll
    for (int i = 0; i < 8; i++) {
        const int m = bm + ty * 8 + i;
        const int l = m >> 2;           // m / B
        const int b = m & 3;            // m % B
#pragma unroll
        for (int j = 0; j < 4; j++) {
            float2 p = unpack2(acc2[i][j]);
            const int n0 = bn + tx * 8 + 2 * j;
            {
                const int h = n0 >> 6, d = n0 & 63;
                Out[((size_t)(b * Hh + h) * Lq + l) * HD + d] = scale * (p.x + bz[n0]);
            }
            {
                const int n1 = n0 + 1;
                const int h = n1 >> 6, d = n1 & 63;
                Out[((size_t)(b * Hh + h) * Lq + l) * HD + d] = scale * (p.y + bz[n1]);
            }
        }
    }
}

// ---------------------------------------------------------------------------
// Kernel 2: flash attention, fp32 math via packed f32x2. One block =
// (head, 128 q-rows). Each thread owns one q row (q/o packed in registers).
// K/V tiles of 64 in smem, read back as packed u64 pairs.
// ---------------------------------------------------------------------------
__global__ __launch_bounds__(128)
void attn_kernel()
{
    const float* gQ = g_scratch;
    const float* gK = g_scratch + SEG;
    const float* gV = g_scratch + 2 * SEG;
    float*       gO = g_scratch + 3 * SEG;

    const int head = blockIdx.y;
    const int q0   = blockIdx.x * 128;
    const int tid  = threadIdx.x;

    __shared__ __align__(16) float Ks[64][64];
    __shared__ __align__(16) float Vs[64][64];

    // Load my q row pre-packed (bit pattern of 2 floats == packed f32x2).
    u64 qr2[32];
    {
        const ulonglong2* Qp = (const ulonglong2*)(gQ + ((size_t)head * Lq + q0 + tid) * HD);
#pragma unroll
        for (int i = 0; i < 16; i++) {
            ulonglong2 t = Qp[i];
            qr2[2*i] = t.x; qr2[2*i+1] = t.y;
        }
    }

    u64 o2[32];
#pragma unroll
    for (int i = 0; i < 32; i++) o2[i] = 0ull;
    float mval = -1e30f, lsum = 0.0f;

    const int jr = tid >> 1;            // 0..63 tile row for coop load
    const int c0 = (tid & 1) * 32;      // half-row offset

    for (int kt = 0; kt < Lq; kt += 64) {
        const float* kp = gK + ((size_t)head * Lq + kt + jr) * HD + c0;
        const float* vp = gV + ((size_t)head * Lq + kt + jr) * HD + c0;
#pragma unroll
        for (int i = 0; i < 8; i++) {
            *(float4*)(&Ks[jr][c0 + i * 4]) = *(const float4*)(kp + i * 4);
            *(float4*)(&Vs[jr][c0 + i * 4]) = *(const float4*)(vp + i * 4);
        }
        __syncthreads();

#pragma unroll 1
        for (int jc = 0; jc < 64; jc += 16) {
            float s[16];
            float cmax = -1e30f;
#pragma unroll
            for (int jj = 0; jj < 16; jj++) {
                u64 a2 = 0ull;
                const ulonglong2* k8 = (const ulonglong2*)(&Ks[jc + jj][0]);
#pragma unroll
                for (int t = 0; t < 16; t++) {
                    ulonglong2 kk2 = k8[t];
                    a2 = ffma2(qr2[2*t],   kk2.x, a2);
                    a2 = ffma2(qr2[2*t+1], kk2.y, a2);
                }
                float2 f = unpack2(a2);
                s[jj] = f.x + f.y;
                cmax = fmaxf(cmax, s[jj]);
            }
            if (cmax > mval) {
                const float corr = __expf(mval - cmax);
                mval = cmax;
                lsum *= corr;
                const u64 c2 = pack2(corr, corr);
#pragma unroll
                for (int i = 0; i < 32; i++) o2[i] = fmul2(o2[i], c2);
            }
#pragma unroll
            for (int jj = 0; jj < 16; jj++) {
                const float p = __expf(s[jj] - mval);
                lsum += p;
                const u64 p2 = pack2(p, p);
                const ulonglong2* v8 = (const ulonglong2*)(&Vs[jc + jj][0]);
#pragma unroll
                for (int t = 0; t < 16; t++) {
                    ulonglong2 vv = v8[t];
                    o2[2*t]   = ffma2(p2, vv.x, o2[2*t]);
                    o2[2*t+1] = ffma2(p2, vv.y, o2[2*t+1]);
                }
            }
        }
        __syncthreads();
    }

    const float inv = 1.0f / lsum;
    const u64 inv2 = pack2(inv, inv);
    ulonglong2* op = (ulonglong2*)(gO + ((size_t)head * Lq + q0 + tid) * HD);
#pragma unroll
    for (int t = 0; t < 16; t++) {
        ulonglong2 r;
        r.x = fmul2(o2[2*t],   inv2);
        r.y = fmul2(o2[2*t+1], inv2);
        op[t] = r;
    }
}

// ---------------------------------------------------------------------------
// Kernel 3: output projection. A[m,k] gathered from g_O (BH,L,HD) layout;
// C[m,n] = sum_k A[m,k]*out_w[n,k] + out_b[n]; out (L,B,E) flat row m.
// ---------------------------------------------------------------------------
__global__ __launch_bounds__(256)
void outproj_kernel(const float* __restrict__ ow,
                    const float* __restrict__ ob,
                    float* __restrict__ out)
{
    const float* gO = g_scratch + 3 * SEG;

    __shared__ __align__(16) float As[8][128];
    __shared__ __align__(16) float Bs[8][128];

    const int bm  = blockIdx.y * 128;
    const int bn  = blockIdx.x * 128;
    const int tid = threadIdx.x;
    const int tx  = tid & 15;
    const int ty  = tid >> 4;

    const int lrow = tid >> 1;
    const int lcol = (tid & 1) * 4;

    u64 acc2[8][4];
#pragma unroll
    for (int i = 0; i < 8; i++)
#pragma unroll
        for (int j = 0; j < 4; j++) acc2[i][j] = 0ull;

    const int m_l  = (bm + lrow);
    const int lA   = m_l >> 2;     // l
    const int bA   = m_l & 3;      // b

    for (int k0 = 0; k0 < Ee; k0 += 8) {
        const int kidx = k0 + lcol;
        const int h = kidx >> 6;
        const int d = kidx & 63;
        float4 a4 = *(const float4*)(gO + ((size_t)(bA * Hh + h) * Lq + lA) * HD + d);
        As[lcol + 0][lrow] = a4.x;
        As[lcol + 1][lrow] = a4.y;
        As[lcol + 2][lrow] = a4.z;
        As[lcol + 3][lrow] = a4.w;
        float4 b4 = *(const float4*)(ow + (size_t)(bn + lrow) * Ee + k0 + lcol);
        Bs[lcol + 0][lrow] = b4.x;
        Bs[lcol + 1][lrow] = b4.y;
        Bs[lcol + 2][lrow] = b4.z;
        Bs[lcol + 3][lrow] = b4.w;
        __syncthreads();

        float4 a0 = *(const float4*)(&As[0][ty * 8]);
        float4 a1 = *(const float4*)(&As[0][ty * 8 + 4]);
        ulonglong2 bb0 = *(const ulonglong2*)(&Bs[0][tx * 8]);
        ulonglong2 bb1 = *(const ulonglong2*)(&Bs[0][tx * 8 + 4]);
#pragma unroll
        for (int kk = 0; kk < 8; kk++) {
            u64 ab[8];
            ab[0] = pack2(a0.x, a0.x); ab[1] = pack2(a0.y, a0.y);
            ab[2] = pack2(a0.z, a0.z); ab[3] = pack2(a0.w, a0.w);
            ab[4] = pack2(a1.x, a1.x); ab[5] = pack2(a1.y, a1.y);
            ab[6] = pack2(a1.z, a1.z); ab[7] = pack2(a1.w, a1.w);
            u64 br2[4];
            br2[0] = bb0.x; br2[1] = bb0.y; br2[2] = bb1.x; br2[3] = bb1.y;
            if (kk < 7) {
                a0  = *(const float4*)(&As[kk + 1][ty * 8]);
                a1  = *(const float4*)(&As[kk + 1][ty * 8 + 4]);
                bb0 = *(const ulonglong2*)(&Bs[kk + 1][tx * 8]);
                bb1 = *(const ulonglong2*)(&Bs[kk + 1][tx * 8 + 4]);
            }
#pragma unroll
            for (int i = 0; i < 8; i++)
#pragma unroll
                for (int j = 0; j < 4; j++)
                    acc2[i][j] = ffma2(ab[i], br2[j], acc2[i][j]);
        }
        __syncthreads();
    }

#pragma unroll
    for (int i = 0; i < 8; i++) {
        const int m = bm + ty * 8 + i;
#pragma unroll
        for (int j = 0; j < 4; j++) {
            float2 p = unpack2(acc2[i][j]);
            const int n0 = bn + tx * 8 + 2 * j;
            out[(size_t)m * Ee + n0]     = p.x + ob[n0];
            out[(size_t)m * Ee + n0 + 1] = p.y + ob[n0 + 1];
        }
    }
}

// ---------------------------------------------------------------------------
// Launch
// Inputs: 0=q, 1=k, 2=v, 3=in_proj_weight, 4=in_proj_bias, 5=out_w, 6=out_b
// ---------------------------------------------------------------------------
extern "C" void kernel_launch(void* const* d_in, const int* in_sizes, int n_in,
                              void* d_out, int out_size)
{
    const float* q  = (const float*)d_in[0];
    const float* k  = (const float*)d_in[1];
    const float* v  = (const float*)d_in[2];
    const float* w  = (const float*)d_in[3];
    const float* bi = (const float*)d_in[4];
    const float* ow = (const float*)d_in[5];
    const float* ob = (const float*)d_in[6];
    float* out = (float*)d_out;

    dim3 gp(Ee / 128, Mrows / 128, 3);
    proj_kernel<<<gp, 256>>>(q, k, v, w, bi);

    dim3 ga(Lq / 128, BHh);
    attn_kernel<<<ga, 128>>>();

    dim3 go(Ee / 128, Mrows / 128);
    outproj_kernel<<<go, 256>>>(ow, ob, out);
}

// round 6
// speedup vs baseline: 1.2329x; 1.2208x over previous
#include <cuda_runtime.h>
#include <cuda_bf16.h>
#include <cstdint>

// Problem constants
#define Lq   2048
#define Bb   4
#define Ee   1024
#define Hh   16
#define HD   64
#define BHh  64            // Bb*Hh
#define Mrows (Lq*Bb)      // 8192
#define SEG  ((size_t)BHh * Lq * HD)     // 8388608
#define ME   ((size_t)Mrows * Ee)        // 8388608
#define EE   ((size_t)Ee * Ee)           // 1048576

// f32 scratch: Q,K,V in (BH, L, HD)
__device__ float g_scratch[3 * SEG];
// bf16 split operands
__device__ __nv_bfloat16 g_xh[3 * ME], g_xl[3 * ME];       // q,k,v activations
__device__ __nv_bfloat16 g_wh[4 * EE], g_wl[4 * EE];       // in_proj_weight (3EE) + out_w (EE)
__device__ __nv_bfloat16 g_oh[SEG],    g_ol[SEG];          // attention output

typedef unsigned long long u64;

// ---------------------------------------------------------------------------
// helpers
// ---------------------------------------------------------------------------
__device__ __forceinline__ uint32_t smem_u32(const void* p) {
    uint32_t a;
    asm("{ .reg .u64 t; cvta.to.shared.u64 t, %1; cvt.u32.u64 %0, t; }"
        : "=r"(a) : "l"(p));
    return a;
}
#define CP16(dst, src) asm volatile("cp.async.cg.shared.global [%0], [%1], 16;" :: "r"(dst), "l"(src))
#define CP_COMMIT()    asm volatile("cp.async.commit_group;" ::: "memory")
#define CP_WAIT(n)     asm volatile("cp.async.wait_group %0;" :: "n"(n) : "memory")

__device__ __forceinline__ void mma_bf16(float* c, const uint32_t* a, const uint32_t* b) {
    asm volatile(
        "mma.sync.aligned.m16n8k16.row.col.f32.bf16.bf16.f32 "
        "{%0,%1,%2,%3}, {%4,%5,%6,%7}, {%8,%9}, {%0,%1,%2,%3};"
        : "+f"(c[0]), "+f"(c[1]), "+f"(c[2]), "+f"(c[3])
        : "r"(a[0]), "r"(a[1]), "r"(a[2]), "r"(a[3]), "r"(b[0]), "r"(b[1]));
}

// packed f32x2 for attention
__device__ __forceinline__ u64 pack2(float lo, float hi) {
    u64 r; asm("mov.b64 %0, {%1, %2};" : "=l"(r) : "f"(lo), "f"(hi)); return r;
}
__device__ __forceinline__ float2 unpack2(u64 v) {
    float2 f; asm("mov.b64 {%0, %1}, %2;" : "=f"(f.x), "=f"(f.y) : "l"(v)); return f;
}
__device__ __forceinline__ u64 ffma2(u64 a, u64 b, u64 c) {
    u64 d; asm("fma.rn.f32x2 %0, %1, %2, %3;" : "=l"(d) : "l"(a), "l"(b), "l"(c)); return d;
}
__device__ __forceinline__ u64 fmul2(u64 a, u64 b) {
    u64 d; asm("mul.rn.f32x2 %0, %1, %2;" : "=l"(d) : "l"(a), "l"(b)); return d;
}

__device__ __forceinline__ void split_bf(float x, unsigned short& h, unsigned short& l) {
    h = __bfloat16_as_ushort(__float2bfloat16(x));
    float r = x - __bfloat162float(__ushort_as_bfloat16(h));
    l = __bfloat16_as_ushort(__float2bfloat16(r));
}

// ---------------------------------------------------------------------------
// prep: split all GEMM operands into bf16 hi/lo. One float4 per thread.
// ---------------------------------------------------------------------------
#define NX4 ((3 * ME + 4 * EE) / 4)     // 7340032
__global__ __launch_bounds__(256)
void prep_kernel(const float* __restrict__ q, const float* __restrict__ k,
                 const float* __restrict__ v, const float* __restrict__ w,
                 const float* __restrict__ ow)
{
    size_t i4 = (size_t)blockIdx.x * 256 + threadIdx.x;
    if (i4 >= NX4) return;
    size_t base = i4 * 4;
    const float* src;
    __nv_bfloat16 *dh, *dl;
    if (base < 3 * ME) {
        size_t z = base / ME, off = base - z * ME;
        src = (z == 0 ? q : z == 1 ? k : v) + off;
        dh = g_xh + base; dl = g_xl + base;
    } else {
        size_t off = base - 3 * ME;
        src = (off < 3 * EE) ? (w + off) : (ow + (off - 3 * EE));
        dh = g_wh + off; dl = g_wl + off;
    }
    float4 f = *(const float4*)src;
    unsigned short h0,h1,h2,h3,l0,l1,l2,l3;
    split_bf(f.x, h0, l0); split_bf(f.y, h1, l1);
    split_bf(f.z, h2, l2); split_bf(f.w, h3, l3);
    uint2 ph = make_uint2((uint32_t)h0 | ((uint32_t)h1 << 16),
                          (uint32_t)h2 | ((uint32_t)h3 << 16));
    uint2 pl = make_uint2((uint32_t)l0 | ((uint32_t)l1 << 16),
                          (uint32_t)l2 | ((uint32_t)l3 << 16));
    *(uint2*)dh = ph;
    *(uint2*)dl = pl;
}

// ---------------------------------------------------------------------------
// GEMM on mma.sync bf16x3. CTA tile 128x128, K-iter 64, 2-stage cp.async.
// MODE 0: QKV projection (z = blockIdx.z), MODE 1: output projection.
// smem tile rows padded to 144B (conflict-free fragment loads).
// ---------------------------------------------------------------------------
#define TP    (128 * 144)          // one tile: 18432 B
#define STG   (4 * TP)             // AH AL BH BL: 73728 B
#define SMEM_T (2 * STG)           // 147456 B
#define NIT   16                   // K iterations (1024 / 64)

template<int MODE>
__global__ __launch_bounds__(256)
void gemm_tc(const float* __restrict__ bias, float* __restrict__ outp)
{
    extern __shared__ __align__(128) char smem[];
    const uint32_t sbase = smem_u32(smem);

    const int z   = (MODE == 0) ? blockIdx.z : 0;
    const int bm  = blockIdx.y * 128;
    const int bn  = blockIdx.x * 128;
    const int tid = threadIdx.x;
    const int wid  = tid >> 5;
    const int lane = tid & 31;
    const int wm = wid & 3;          // warp m index (4)
    const int wn = wid >> 2;         // warp n index (2)

    const int r    = tid >> 1;       // 0..127 (row for coop loads)
    const int half = tid & 1;        // 32-elem half of a 64-col row

    // global row bases for cp.async
    const __nv_bfloat16 *a_h, *a_l;
    if (MODE == 0) {
        size_t arow = (size_t)z * ME + (size_t)(bm + r) * Ee + half * 32;
        a_h = g_xh + arow; a_l = g_xl + arow;
    } else {
        const int mrow = bm + r;
        const int lA = mrow >> 2, bA = mrow & 3;
        size_t arow = ((size_t)bA * Hh * Lq + lA) * HD + half * 32;   // + it*(Lq*HD) per iter (head stride)
        a_h = g_oh + arow; a_l = g_ol + arow;
    }
    const size_t brow = (size_t)((MODE == 0 ? z * Ee : 3 * Ee) + bn + r) * Ee + half * 32;
    const __nv_bfloat16* b_h = g_wh + brow;
    const __nv_bfloat16* b_l = g_wl + brow;

    // per-iter source stride (elements)
    const size_t a_step = (MODE == 0) ? 64 : (size_t)Lq * HD;  // MODE1: next head
    const size_t b_step = 64;

    const uint32_t dst_r = sbase + r * 144 + half * 64;

    float acc[2][8][4];
#pragma unroll
    for (int i = 0; i < 2; i++)
#pragma unroll
        for (int j = 0; j < 8; j++)
#pragma unroll
            for (int t = 0; t < 4; t++) acc[i][j][t] = 0.0f;

    auto load_stage = [&](int it, int s) {
        const uint32_t d = dst_r + s * STG;
        const __nv_bfloat16* pa_h = a_h + (size_t)it * a_step;
        const __nv_bfloat16* pa_l = a_l + (size_t)it * a_step;
        const __nv_bfloat16* pb_h = b_h + (size_t)it * b_step;
        const __nv_bfloat16* pb_l = b_l + (size_t)it * b_step;
#pragma unroll
        for (int c = 0; c < 4; c++) {
            CP16(d + 0 * TP + c * 16, pa_h + c * 8);
            CP16(d + 1 * TP + c * 16, pa_l + c * 8);
            CP16(d + 2 * TP + c * 16, pb_h + c * 8);
            CP16(d + 3 * TP + c * 16, pb_l + c * 8);
        }
    };

    const int g  = lane >> 2;
    const int tc = lane & 3;

    load_stage(0, 0); CP_COMMIT();

    for (int it = 0; it < NIT; it++) {
        if (it + 1 < NIT) { load_stage(it + 1, (it + 1) & 1); CP_COMMIT(); CP_WAIT(1); }
        else              { CP_WAIT(0); }
        __syncthreads();

        const char* sa_h = smem + (it & 1) * STG + 0 * TP;
        const char* sa_l = smem + (it & 1) * STG + 1 * TP;
        const char* sb_h = smem + (it & 1) * STG + 2 * TP;
        const char* sb_l = smem + (it & 1) * STG + 3 * TP;

#pragma unroll
        for (int ks = 0; ks < 4; ks++) {
            const int cbyte = (ks * 16 + tc * 2) * 2;
            uint32_t ah[2][4], al[2][4];
#pragma unroll
            for (int mt = 0; mt < 2; mt++) {
                const int r0 = wm * 32 + mt * 16 + g;
                const char* ph = sa_h + r0 * 144 + cbyte;
                const char* pl = sa_l + r0 * 144 + cbyte;
                ah[mt][0] = *(const uint32_t*)(ph);
                ah[mt][1] = *(const uint32_t*)(ph + 8 * 144);
                ah[mt][2] = *(const uint32_t*)(ph + 16);
                ah[mt][3] = *(const uint32_t*)(ph + 8 * 144 + 16);
                al[mt][0] = *(const uint32_t*)(pl);
                al[mt][1] = *(const uint32_t*)(pl + 8 * 144);
                al[mt][2] = *(const uint32_t*)(pl + 16);
                al[mt][3] = *(const uint32_t*)(pl + 8 * 144 + 16);
            }
#pragma unroll
            for (int nt = 0; nt < 8; nt++) {
                const int rn = wn * 64 + nt * 8 + g;
                const char* pbh = sb_h + rn * 144 + cbyte;
                const char* pbl = sb_l + rn * 144 + cbyte;
                uint32_t bh[2], bl[2];
                bh[0] = *(const uint32_t*)(pbh);
                bh[1] = *(const uint32_t*)(pbh + 16);
                bl[0] = *(const uint32_t*)(pbl);
                bl[1] = *(const uint32_t*)(pbl + 16);
#pragma unroll
                for (int mt = 0; mt < 2; mt++) {
                    mma_bf16(acc[mt][nt], ah[mt], bh);
                    mma_bf16(acc[mt][nt], ah[mt], bl);
                    mma_bf16(acc[mt][nt], al[mt], bh);
                }
            }
        }
        __syncthreads();
    }

    // epilogue
    const float scale = (MODE == 0 && z == 0) ? 0.125f : 1.0f;
#pragma unroll
    for (int mt = 0; mt < 2; mt++) {
#pragma unroll
        for (int half_m = 0; half_m < 2; half_m++) {
            const int m = bm + wm * 32 + mt * 16 + g + half_m * 8;
#pragma unroll
            for (int nt = 0; nt < 8; nt++) {
                const int n = bn + wn * 64 + nt * 8 + tc * 2;
                const float c0 = acc[mt][nt][half_m * 2 + 0];
                const float c1 = acc[mt][nt][half_m * 2 + 1];
                if (MODE == 0) {
                    const int l = m >> 2, b = m & 3;
                    const int h = n >> 6, d = n & 63;
                    float2 t;
                    t.x = scale * (c0 + bias[z * Ee + n]);
                    t.y = scale * (c1 + bias[z * Ee + n + 1]);
                    *(float2*)&g_scratch[(size_t)z * SEG +
                        ((size_t)(b * Hh + h) * Lq + l) * HD + d] = t;
                } else {
                    float2 t;
                    t.x = c0 + bias[n];
                    t.y = c1 + bias[n + 1];
                    *(float2*)&outp[(size_t)m * Ee + n] = t;
                }
            }
        }
    }
}

// ---------------------------------------------------------------------------
// flash attention (passing f32x2 version); epilogue writes bf16 hi/lo O.
// ---------------------------------------------------------------------------
__global__ __launch_bounds__(128)
void attn_kernel()
{
    const float* gQ = g_scratch;
    const float* gK = g_scratch + SEG;
    const float* gV = g_scratch + 2 * SEG;

    const int head = blockIdx.y;
    const int q0   = blockIdx.x * 128;
    const int tid  = threadIdx.x;

    __shared__ __align__(16) float Ks[64][64];
    __shared__ __align__(16) float Vs[64][64];

    u64 qr2[32];
    {
        const ulonglong2* Qp = (const ulonglong2*)(gQ + ((size_t)head * Lq + q0 + tid) * HD);
#pragma unroll
        for (int i = 0; i < 16; i++) {
            ulonglong2 t = Qp[i];
            qr2[2*i] = t.x; qr2[2*i+1] = t.y;
        }
    }

    u64 o2[32];
#pragma unroll
    for (int i = 0; i < 32; i++) o2[i] = 0ull;
    float mval = -1e30f, lsum = 0.0f;

    const int jr = tid >> 1;
    const int c0 = (tid & 1) * 32;

    for (int kt = 0; kt < Lq; kt += 64) {
        const float* kp = gK + ((size_t)head * Lq + kt + jr) * HD + c0;
        const float* vp = gV + ((size_t)head * Lq + kt + jr) * HD + c0;
#pragma unroll
        for (int i = 0; i < 8; i++) {
            *(float4*)(&Ks[jr][c0 + i * 4]) = *(const float4*)(kp + i * 4);
            *(float4*)(&Vs[jr][c0 + i * 4]) = *(const float4*)(vp + i * 4);
        }
        __syncthreads();

#pragma unroll 1
        for (int jc = 0; jc < 64; jc += 16) {
            float s[16];
            float cmax = -1e30f;
#pragma unroll
            for (int jj = 0; jj < 16; jj++) {
                u64 a2 = 0ull;
                const ulonglong2* k8 = (const ulonglong2*)(&Ks[jc + jj][0]);
#pragma unroll
                for (int t = 0; t < 16; t++) {
                    ulonglong2 kk2 = k8[t];
                    a2 = ffma2(qr2[2*t],   kk2.x, a2);
                    a2 = ffma2(qr2[2*t+1], kk2.y, a2);
                }
                float2 f = unpack2(a2);
                s[jj] = f.x + f.y;
                cmax = fmaxf(cmax, s[jj]);
            }
            if (cmax > mval) {
                const float corr = __expf(mval - cmax);
                mval = cmax;
                lsum *= corr;
                const u64 c2 = pack2(corr, corr);
#pragma unroll
                for (int i = 0; i < 32; i++) o2[i] = fmul2(o2[i], c2);
            }
#pragma unroll
            for (int jj = 0; jj < 16; jj++) {
                const float p = __expf(s[jj] - mval);
                lsum += p;
                const u64 p2 = pack2(p, p);
                const ulonglong2* v8 = (const ulonglong2*)(&Vs[jc + jj][0]);
#pragma unroll
                for (int t = 0; t < 16; t++) {
                    ulonglong2 vv = v8[t];
                    o2[2*t]   = ffma2(p2, vv.x, o2[2*t]);
                    o2[2*t+1] = ffma2(p2, vv.y, o2[2*t+1]);
                }
            }
        }
        __syncthreads();
    }

    const float inv = 1.0f / lsum;
    const size_t orow = ((size_t)head * Lq + q0 + tid) * HD;
#pragma unroll
    for (int t = 0; t < 8; t++) {
        float2 f0 = unpack2(o2[4*t + 0]);
        float2 f1 = unpack2(o2[4*t + 1]);
        float2 f2 = unpack2(o2[4*t + 2]);
        float2 f3 = unpack2(o2[4*t + 3]);
        float x[8] = { f0.x*inv, f0.y*inv, f1.x*inv, f1.y*inv,
                       f2.x*inv, f2.y*inv, f3.x*inv, f3.y*inv };
        unsigned short h[8], l[8];
#pragma unroll
        for (int i = 0; i < 8; i++) split_bf(x[i], h[i], l[i]);
        uint4 ph = make_uint4((uint32_t)h[0] | ((uint32_t)h[1] << 16),
                              (uint32_t)h[2] | ((uint32_t)h[3] << 16),
                              (uint32_t)h[4] | ((uint32_t)h[5] << 16),
                              (uint32_t)h[6] | ((uint32_t)h[7] << 16));
        uint4 pl = make_uint4((uint32_t)l[0] | ((uint32_t)l[1] << 16),
                              (uint32_t)l[2] | ((uint32_t)l[3] << 16),
                              (uint32_t)l[4] | ((uint32_t)l[5] << 16),
                              (uint32_t)l[6] | ((uint32_t)l[7] << 16));
        *(uint4*)&g_oh[orow + t * 8] = ph;
        *(uint4*)&g_ol[orow + t * 8] = pl;
    }
}

// ---------------------------------------------------------------------------
// Launch
// Inputs: 0=q, 1=k, 2=v, 3=in_proj_weight, 4=in_proj_bias, 5=out_w, 6=out_b
// ---------------------------------------------------------------------------
extern "C" void kernel_launch(void* const* d_in, const int* in_sizes, int n_in,
                              void* d_out, int out_size)
{
    const float* q  = (const float*)d_in[0];
    const float* k  = (const float*)d_in[1];
    const float* v  = (const float*)d_in[2];
    const float* w  = (const float*)d_in[3];
    const float* bi = (const float*)d_in[4];
    const float* ow = (const float*)d_in[5];
    const float* ob = (const float*)d_in[6];
    float* out = (float*)d_out;

    static bool configured = false;
    if (!configured) {
        cudaFuncSetAttribute(gemm_tc<0>, cudaFuncAttributeMaxDynamicSharedMemorySize, SMEM_T);
        cudaFuncSetAttribute(gemm_tc<1>, cudaFuncAttributeMaxDynamicSharedMemorySize, SMEM_T);
        configured = true;
    }

    prep_kernel<<<(unsigned)((NX4 + 255) / 256), 256>>>(q, k, v, w, ow);

    dim3 gp(Ee / 128, Mrows / 128, 3);
    gemm_tc<0><<<gp, 256, SMEM_T>>>(bi, nullptr);

    dim3 ga(Lq / 128, BHh);
    attn_kernel<<<ga, 128>>>();

    dim3 go(Ee / 128, Mrows / 128);
    gemm_tc<1><<<go, 256, SMEM_T>>>(ob, out);
}

// round 10
// speedup vs baseline: 2.9651x; 2.4050x over previous
#include <cuda_runtime.h>
#include <cuda_bf16.h>
#include <cstdint>

// Problem constants
#define Lq   2048
#define Bb   4
#define Ee   1024
#define Hh   16
#define HD   64
#define BHh  64            // Bb*Hh
#define Mrows (Lq*Bb)      // 8192
#define SEG  ((size_t)BHh * Lq * HD)     // 8388608
#define ME   ((size_t)Mrows * Ee)        // 8388608
#define EE   ((size_t)Ee * Ee)           // 1048576

// bf16 split operands
__device__ __nv_bfloat16 g_xh[3 * ME], g_xl[3 * ME];       // q,k,v activations (prep)
__device__ __nv_bfloat16 g_wh[4 * EE], g_wl[4 * EE];       // in_proj_weight (3EE) + out_w (EE)
__device__ __nv_bfloat16 g_qkvh[3 * SEG], g_qkvl[3 * SEG]; // projected Q,K,V (BH,L,HD)
__device__ __nv_bfloat16 g_oh[SEG], g_ol[SEG];             // attention output

typedef unsigned long long u64;

// ---------------------------------------------------------------------------
// helpers
// ---------------------------------------------------------------------------
__device__ __forceinline__ uint32_t smem_u32(const void* p) {
    uint32_t a;
    asm("{ .reg .u64 t; cvta.to.shared.u64 t, %1; cvt.u32.u64 %0, t; }"
        : "=r"(a) : "l"(p));
    return a;
}
#define CP16(dst, src) asm volatile("cp.async.cg.shared.global [%0], [%1], 16;" :: "r"(dst), "l"(src))
#define CP_COMMIT()    asm volatile("cp.async.commit_group;" ::: "memory")
#define CP_WAIT(n)     asm volatile("cp.async.wait_group %0;" :: "n"(n) : "memory")

__device__ __forceinline__ void mma_bf16(float* c, const uint32_t* a, const uint32_t* b) {
    asm volatile(
        "mma.sync.aligned.m16n8k16.row.col.f32.bf16.bf16.f32 "
        "{%0,%1,%2,%3}, {%4,%5,%6,%7}, {%8,%9}, {%0,%1,%2,%3};"
        : "+f"(c[0]), "+f"(c[1]), "+f"(c[2]), "+f"(c[3])
        : "r"(a[0]), "r"(a[1]), "r"(a[2]), "r"(a[3]), "r"(b[0]), "r"(b[1]));
}

__device__ __forceinline__ void split_bf(float x, unsigned short& h, unsigned short& l) {
    h = __bfloat16_as_ushort(__float2bfloat16(x));
    float r = x - __bfloat162float(__ushort_as_bfloat16(h));
    l = __bfloat16_as_ushort(__float2bfloat16(r));
}
// pack two floats -> (hi u32, lo u32) of bf16 pairs
__device__ __forceinline__ void split_pack2(float f0, float f1, uint32_t& hi, uint32_t& lo) {
    unsigned short h0, h1, l0, l1;
    split_bf(f0, h0, l0); split_bf(f1, h1, l1);
    hi = (uint32_t)h0 | ((uint32_t)h1 << 16);
    lo = (uint32_t)l0 | ((uint32_t)l1 << 16);
}
__device__ __forceinline__ uint32_t get16(const uint4& v, int j) {
    uint32_t w = ((j >> 1) == 0) ? v.x : ((j >> 1) == 1) ? v.y : ((j >> 1) == 2) ? v.z : v.w;
    return (j & 1) ? (w >> 16) : (w & 0xffffu);
}

// ---------------------------------------------------------------------------
// prep: split activations + weights into bf16 hi/lo. One float4 per thread.
// ---------------------------------------------------------------------------
#define NX4 ((3 * ME + 4 * EE) / 4)
__global__ __launch_bounds__(256)
void prep_kernel(const float* __restrict__ q, const float* __restrict__ k,
                 const float* __restrict__ v, const float* __restrict__ w,
                 const float* __restrict__ ow)
{
    size_t i4 = (size_t)blockIdx.x * 256 + threadIdx.x;
    if (i4 >= NX4) return;
    size_t base = i4 * 4;
    const float* src;
    __nv_bfloat16 *dh, *dl;
    if (base < 3 * ME) {
        size_t z = base / ME, off = base - z * ME;
        src = (z == 0 ? q : z == 1 ? k : v) + off;
        dh = g_xh + base; dl = g_xl + base;
    } else {
        size_t off = base - 3 * ME;
        src = (off < 3 * EE) ? (w + off) : (ow + (off - 3 * EE));
        dh = g_wh + off; dl = g_wl + off;
    }
    float4 f = *(const float4*)src;
    uint32_t h0, l0, h1, l1;
    split_pack2(f.x, f.y, h0, l0);
    split_pack2(f.z, f.w, h1, l1);
    *(uint2*)dh = make_uint2(h0, h1);
    *(uint2*)dl = make_uint2(l0, l1);
}

// ---------------------------------------------------------------------------
// GEMM on mma.sync bf16x3. CTA tile 128x128, K-iter 64, 2-stage cp.async.
// MODE 0: QKV projection (writes bf16 hi/lo Q,K,V), MODE 1: out projection.
// ---------------------------------------------------------------------------
#define TP    (128 * 144)
#define STG   (4 * TP)
#define SMEM_T (2 * STG)
#define NIT   16

template<int MODE>
__global__ __launch_bounds__(256)
void gemm_tc(const float* __restrict__ bias, float* __restrict__ outp)
{
    extern __shared__ __align__(128) char smem[];
    const uint32_t sbase = smem_u32(smem);

    const int z   = (MODE == 0) ? blockIdx.z : 0;
    const int bm  = blockIdx.y * 128;
    const int bn  = blockIdx.x * 128;
    const int tid = threadIdx.x;
    const int wid  = tid >> 5;
    const int lane = tid & 31;
    const int wm = wid & 3;
    const int wn = wid >> 2;

    const int r    = tid >> 1;
    const int half = tid & 1;

    const __nv_bfloat16 *a_h, *a_l;
    if (MODE == 0) {
        size_t arow = (size_t)z * ME + (size_t)(bm + r) * Ee + half * 32;
        a_h = g_xh + arow; a_l = g_xl + arow;
    } else {
        const int mrow = bm + r;
        const int lA = mrow >> 2, bA = mrow & 3;
        size_t arow = ((size_t)bA * Hh * Lq + lA) * HD + half * 32;
        a_h = g_oh + arow; a_l = g_ol + arow;
    }
    const size_t brow = (size_t)((MODE == 0 ? z * Ee : 3 * Ee) + bn + r) * Ee + half * 32;
    const __nv_bfloat16* b_h = g_wh + brow;
    const __nv_bfloat16* b_l = g_wl + brow;

    const size_t a_step = (MODE == 0) ? 64 : (size_t)Lq * HD;
    const size_t b_step = 64;

    const uint32_t dst_r = sbase + r * 144 + half * 64;

    float acc[2][8][4];
#pragma unroll
    for (int i = 0; i < 2; i++)
#pragma unroll
        for (int j = 0; j < 8; j++)
#pragma unroll
            for (int t = 0; t < 4; t++) acc[i][j][t] = 0.0f;

    auto load_stage = [&](int it, int s) {
        const uint32_t d = dst_r + s * STG;
        const __nv_bfloat16* pa_h = a_h + (size_t)it * a_step;
        const __nv_bfloat16* pa_l = a_l + (size_t)it * a_step;
        const __nv_bfloat16* pb_h = b_h + (size_t)it * b_step;
        const __nv_bfloat16* pb_l = b_l + (size_t)it * b_step;
#pragma unroll
        for (int c = 0; c < 4; c++) {
            CP16(d + 0 * TP + c * 16, pa_h + c * 8);
            CP16(d + 1 * TP + c * 16, pa_l + c * 8);
            CP16(d + 2 * TP + c * 16, pb_h + c * 8);
            CP16(d + 3 * TP + c * 16, pb_l + c * 8);
        }
    };

    const int g  = lane >> 2;
    const int tc = lane & 3;

    load_stage(0, 0); CP_COMMIT();

    for (int it = 0; it < NIT; it++) {
        if (it + 1 < NIT) { load_stage(it + 1, (it + 1) & 1); CP_COMMIT(); CP_WAIT(1); }
        else              { CP_WAIT(0); }
        __syncthreads();

        const char* sa_h = smem + (it & 1) * STG + 0 * TP;
        const char* sa_l = smem + (it & 1) * STG + 1 * TP;
        const char* sb_h = smem + (it & 1) * STG + 2 * TP;
        const char* sb_l = smem + (it & 1) * STG + 3 * TP;

#pragma unroll
        for (int ks = 0; ks < 4; ks++) {
            const int cbyte = (ks * 16 + tc * 2) * 2;
            uint32_t ah[2][4], al[2][4];
#pragma unroll
            for (int mt = 0; mt < 2; mt++) {
                const int r0 = wm * 32 + mt * 16 + g;
                const char* ph = sa_h + r0 * 144 + cbyte;
                const char* pl = sa_l + r0 * 144 + cbyte;
                ah[mt][0] = *(const uint32_t*)(ph);
                ah[mt][1] = *(const uint32_t*)(ph + 8 * 144);
                ah[mt][2] = *(const uint32_t*)(ph + 16);
                ah[mt][3] = *(const uint32_t*)(ph + 8 * 144 + 16);
                al[mt][0] = *(const uint32_t*)(pl);
                al[mt][1] = *(const uint32_t*)(pl + 8 * 144);
                al[mt][2] = *(const uint32_t*)(pl + 16);
                al[mt][3] = *(const uint32_t*)(pl + 8 * 144 + 16);
            }
#pragma unroll
            for (int nt = 0; nt < 8; nt++) {
                const int rn = wn * 64 + nt * 8 + g;
                const char* pbh = sb_h + rn * 144 + cbyte;
                const char* pbl = sb_l + rn * 144 + cbyte;
                uint32_t bh[2], bl[2];
                bh[0] = *(const uint32_t*)(pbh);
                bh[1] = *(const uint32_t*)(pbh + 16);
                bl[0] = *(const uint32_t*)(pbl);
                bl[1] = *(const uint32_t*)(pbl + 16);
#pragma unroll
                for (int mt = 0; mt < 2; mt++) {
                    mma_bf16(acc[mt][nt], ah[mt], bh);
                    mma_bf16(acc[mt][nt], ah[mt], bl);
                    mma_bf16(acc[mt][nt], al[mt], bh);
                }
            }
        }
        __syncthreads();
    }

    const float scale = (MODE == 0 && z == 0) ? 0.125f : 1.0f;
#pragma unroll
    for (int mt = 0; mt < 2; mt++) {
#pragma unroll
        for (int half_m = 0; half_m < 2; half_m++) {
            const int m = bm + wm * 32 + mt * 16 + g + half_m * 8;
#pragma unroll
            for (int nt = 0; nt < 8; nt++) {
                const int n = bn + wn * 64 + nt * 8 + tc * 2;
                const float c0 = acc[mt][nt][half_m * 2 + 0];
                const float c1 = acc[mt][nt][half_m * 2 + 1];
                if (MODE == 0) {
                    const int l = m >> 2, b = m & 3;
                    const int h = n >> 6, d = n & 63;
                    float v0 = scale * (c0 + bias[z * Ee + n]);
                    float v1 = scale * (c1 + bias[z * Ee + n + 1]);
                    uint32_t hi, lo;
                    split_pack2(v0, v1, hi, lo);
                    size_t addr = (size_t)z * SEG + ((size_t)(b * Hh + h) * Lq + l) * HD + d;
                    *(uint32_t*)&g_qkvh[addr] = hi;
                    *(uint32_t*)&g_qkvl[addr] = lo;
                } else {
                    float2 t;
                    t.x = c0 + bias[n];
                    t.y = c1 + bias[n + 1];
                    *(float2*)&outp[(size_t)m * Ee + n] = t;
                }
            }
        }
    }
}

// ---------------------------------------------------------------------------
// Flash attention on mma.sync bf16x3.
// CTA = (head, 128 q rows), 8 warps x 16 rows. K-tile = 128 tokens.
// K smem token-major (144B rows); V smem transposed hd-major (272B rows).
// S C-fragments ARE P A-fragments (register-only softmax).
// ---------------------------------------------------------------------------
#define TKT    128
#define KROW   144
#define VTROW  272
#define SM_KH  0
#define SM_KL  (SM_KH + TKT * KROW)       // 18432
#define SM_VTH (SM_KL + TKT * KROW)       // 36864
#define SM_VTL (SM_VTH + 64 * VTROW)      // 54272
#define SM_ATTN (SM_VTL + 64 * VTROW)     // 71680

__global__ __launch_bounds__(256)
void attn_mma()
{
    extern __shared__ __align__(128) char smem[];
    const uint32_t sb = smem_u32(smem);

    const int head = blockIdx.y;
    const int q0   = blockIdx.x * 128;
    const int tid  = threadIdx.x;
    const int wid  = tid >> 5;
    const int lane = tid & 31;
    const int g    = lane >> 2;
    const int tc   = lane & 3;

    const __nv_bfloat16* Qh = g_qkvh;
    const __nv_bfloat16* Ql = g_qkvl;
    const __nv_bfloat16* Kh = g_qkvh + SEG;
    const __nv_bfloat16* Kl = g_qkvl + SEG;
    const __nv_bfloat16* Vh = g_qkvh + 2 * SEG;
    const __nv_bfloat16* Vl = g_qkvl + 2 * SEG;

    // Q fragments in registers (per warp: 16 rows x 64 hd)
    uint32_t qa_h[4][4], qa_l[4][4];
    {
        const size_t r0 = (size_t)head * Lq + q0 + wid * 16 + g;
        const size_t r1 = r0 + 8;
#pragma unroll
        for (int ks = 0; ks < 4; ks++) {
            const int c0 = ks * 16 + tc * 2;
            qa_h[ks][0] = *(const uint32_t*)(Qh + r0 * HD + c0);
            qa_h[ks][1] = *(const uint32_t*)(Qh + r1 * HD + c0);
            qa_h[ks][2] = *(const uint32_t*)(Qh + r0 * HD + c0 + 8);
            qa_h[ks][3] = *(const uint32_t*)(Qh + r1 * HD + c0 + 8);
            qa_l[ks][0] = *(const uint32_t*)(Ql + r0 * HD + c0);
            qa_l[ks][1] = *(const uint32_t*)(Ql + r1 * HD + c0);
            qa_l[ks][2] = *(const uint32_t*)(Ql + r0 * HD + c0 + 8);
            qa_l[ks][3] = *(const uint32_t*)(Ql + r1 * HD + c0 + 8);
        }
    }

    float O[8][4];
#pragma unroll
    for (int i = 0; i < 8; i++)
#pragma unroll
        for (int j = 0; j < 4; j++) O[i][j] = 0.0f;
    float m0 = -1e30f, m1 = -1e30f, l0 = 0.0f, l1 = 0.0f;

    // coop-load assignments
    const int r    = tid >> 1;        // K rows
    const int hc   = tid & 1;
    const int vsp  = tid >> 7;        // V split (0=hi,1=lo)
    const int vidx = tid & 127;
    const int tb   = (vidx & 15) * 8; // token block
    const int hb   = (vidx >> 4) * 8; // hd block
    const __nv_bfloat16* Vsrc = vsp ? Vl : Vh;
    const uint32_t vdst = sb + (vsp ? SM_VTL : SM_VTH);

    for (int kt = 0; kt < Lq; kt += TKT) {
        if (kt) __syncthreads();
        // K tile via cp.async (hi + lo)
        {
            const uint32_t dk = sb + r * KROW + hc * 64;
            const size_t src = ((size_t)head * Lq + kt + r) * HD + hc * 32;
#pragma unroll
            for (int c = 0; c < 4; c++) {
                CP16(dk + SM_KH + c * 16, Kh + src + c * 8);
                CP16(dk + SM_KL + c * 16, Kl + src + c * 8);
            }
            CP_COMMIT();
        }
        // V tile transposed (manual LDG + STS)
        {
            uint4 vv[8];
#pragma unroll
            for (int t = 0; t < 8; t++)
                vv[t] = *(const uint4*)(Vsrc + ((size_t)head * Lq + kt + tb + t) * HD + hb);
#pragma unroll
            for (int j = 0; j < 8; j++) {
#pragma unroll
                for (int tp = 0; tp < 4; tp++) {
                    uint32_t w0 = get16(vv[2 * tp], j);
                    uint32_t w1 = get16(vv[2 * tp + 1], j);
                    uint32_t pk = w0 | (w1 << 16);
                    const uint32_t a = vdst + (hb + j) * VTROW + (tb + 2 * tp) * 2;
                    asm volatile("st.shared.b32 [%0], %1;" :: "r"(a), "r"(pk) : "memory");
                }
            }
        }
        CP_WAIT(0);
        __syncthreads();

        // S = Q K^T (16 ntiles of 8 tokens)
        float s[16][4];
#pragma unroll
        for (int nt = 0; nt < 16; nt++) {
            float c[4] = {0.f, 0.f, 0.f, 0.f};
#pragma unroll
            for (int ks = 0; ks < 4; ks++) {
                const char* pb = smem + SM_KH + (nt * 8 + g) * KROW + ks * 32 + tc * 4;
                uint32_t bh[2], bl[2];
                bh[0] = *(const uint32_t*)(pb);
                bh[1] = *(const uint32_t*)(pb + 16);
                bl[0] = *(const uint32_t*)(pb + (SM_KL - SM_KH));
                bl[1] = *(const uint32_t*)(pb + (SM_KL - SM_KH) + 16);
                mma_bf16(c, qa_h[ks], bh);
                mma_bf16(c, qa_h[ks], bl);
                mma_bf16(c, qa_l[ks], bh);
            }
            s[nt][0] = c[0]; s[nt][1] = c[1]; s[nt][2] = c[2]; s[nt][3] = c[3];
        }

        // row maxes (within thread, then quad reduce)
        float tm0 = -1e30f, tm1 = -1e30f;
#pragma unroll
        for (int nt = 0; nt < 16; nt++) {
            tm0 = fmaxf(tm0, fmaxf(s[nt][0], s[nt][1]));
            tm1 = fmaxf(tm1, fmaxf(s[nt][2], s[nt][3]));
        }
        tm0 = fmaxf(tm0, __shfl_xor_sync(0xffffffffu, tm0, 1));
        tm0 = fmaxf(tm0, __shfl_xor_sync(0xffffffffu, tm0, 2));
        tm1 = fmaxf(tm1, __shfl_xor_sync(0xffffffffu, tm1, 1));
        tm1 = fmaxf(tm1, __shfl_xor_sync(0xffffffffu, tm1, 2));

        const float nm0 = fmaxf(m0, tm0);
        const float nm1 = fmaxf(m1, tm1);
        const float cor0 = __expf(m0 - nm0);
        const float cor1 = __expf(m1 - nm1);
        m0 = nm0; m1 = nm1;
        l0 *= cor0; l1 *= cor1;
#pragma unroll
        for (int nt = 0; nt < 8; nt++) {
            O[nt][0] *= cor0; O[nt][1] *= cor0;
            O[nt][2] *= cor1; O[nt][3] *= cor1;
        }

        // exp + pack P fragments (C-frag layout == A-frag layout)
        uint32_t pah[8][4], pal[8][4];
#pragma unroll
        for (int ks = 0; ks < 8; ks++) {
            const float p0 = __expf(s[2 * ks][0] - m0);
            const float p1 = __expf(s[2 * ks][1] - m0);
            const float p2 = __expf(s[2 * ks][2] - m1);
            const float p3 = __expf(s[2 * ks][3] - m1);
            const float p4 = __expf(s[2 * ks + 1][0] - m0);
            const float p5 = __expf(s[2 * ks + 1][1] - m0);
            const float p6 = __expf(s[2 * ks + 1][2] - m1);
            const float p7 = __expf(s[2 * ks + 1][3] - m1);
            l0 += p0 + p1 + p4 + p5;
            l1 += p2 + p3 + p6 + p7;
            split_pack2(p0, p1, pah[ks][0], pal[ks][0]);
            split_pack2(p2, p3, pah[ks][1], pal[ks][1]);
            split_pack2(p4, p5, pah[ks][2], pal[ks][2]);
            split_pack2(p6, p7, pah[ks][3], pal[ks][3]);
        }

        // O += P V (8 hd ntiles x 8 ksteps of 16 tokens)
#pragma unroll
        for (int nt = 0; nt < 8; nt++) {
#pragma unroll
            for (int ks = 0; ks < 8; ks++) {
                const char* pv = smem + SM_VTH + (nt * 8 + g) * VTROW + ks * 32 + tc * 4;
                uint32_t vh2[2], vl2[2];
                vh2[0] = *(const uint32_t*)(pv);
                vh2[1] = *(const uint32_t*)(pv + 16);
                vl2[0] = *(const uint32_t*)(pv + (SM_VTL - SM_VTH));
                vl2[1] = *(const uint32_t*)(pv + (SM_VTL - SM_VTH) + 16);
                mma_bf16(O[nt], pah[ks], vh2);
                mma_bf16(O[nt], pah[ks], vl2);
                mma_bf16(O[nt], pal[ks], vh2);
            }
        }
    }

    // finalize: quad-reduce l, normalize, write split-bf16 O
    l0 += __shfl_xor_sync(0xffffffffu, l0, 1);
    l0 += __shfl_xor_sync(0xffffffffu, l0, 2);
    l1 += __shfl_xor_sync(0xffffffffu, l1, 1);
    l1 += __shfl_xor_sync(0xffffffffu, l1, 2);
    const float inv0 = 1.0f / l0;
    const float inv1 = 1.0f / l1;

    const size_t r0 = (size_t)head * Lq + q0 + wid * 16 + g;
    const size_t r1 = r0 + 8;
#pragma unroll
    for (int nt = 0; nt < 8; nt++) {
        const int col = nt * 8 + tc * 2;
        uint32_t hi, lo;
        split_pack2(O[nt][0] * inv0, O[nt][1] * inv0, hi, lo);
        *(uint32_t*)&g_oh[r0 * HD + col] = hi;
        *(uint32_t*)&g_ol[r0 * HD + col] = lo;
        split_pack2(O[nt][2] * inv1, O[nt][3] * inv1, hi, lo);
        *(uint32_t*)&g_oh[r1 * HD + col] = hi;
        *(uint32_t*)&g_ol[r1 * HD + col] = lo;
    }
}

// ---------------------------------------------------------------------------
// Launch
// Inputs: 0=q, 1=k, 2=v, 3=in_proj_weight, 4=in_proj_bias, 5=out_w, 6=out_b
// ---------------------------------------------------------------------------
extern "C" void kernel_launch(void* const* d_in, const int* in_sizes, int n_in,
                              void* d_out, int out_size)
{
    const float* q  = (const float*)d_in[0];
    const float* k  = (const float*)d_in[1];
    const float* v  = (const float*)d_in[2];
    const float* w  = (const float*)d_in[3];
    const float* bi = (const float*)d_in[4];
    const float* ow = (const float*)d_in[5];
    const float* ob = (const float*)d_in[6];
    float* out = (float*)d_out;

    static bool configured = false;
    if (!configured) {
        cudaFuncSetAttribute(gemm_tc<0>, cudaFuncAttributeMaxDynamicSharedMemorySize, SMEM_T);
        cudaFuncSetAttribute(gemm_tc<1>, cudaFuncAttributeMaxDynamicSharedMemorySize, SMEM_T);
        cudaFuncSetAttribute(attn_mma,   cudaFuncAttributeMaxDynamicSharedMemorySize, SM_ATTN);
        configured = true;
    }

    prep_kernel<<<(unsigned)((NX4 + 255) / 256), 256>>>(q, k, v, w, ow);

    dim3 gp(Ee / 128, Mrows / 128, 3);
    gemm_tc<0><<<gp, 256, SMEM_T>>>(bi, nullptr);

    dim3 ga(Lq / 128, BHh);
    attn_mma<<<ga, 256, SM_ATTN>>>();

    dim3 go(Ee / 128, Mrows / 128);
    gemm_tc<1><<<go, 256, SMEM_T>>>(ob, out);
}